// round 6
// baseline (speedup 1.0000x reference)
#include <cuda_runtime.h>
#include <cstdint>

#define NF     12
#define NPAIR  66
#define NCOMB  781
#define NCOLS  793
#define NROWS  32768
#define WPB    8            // warps per block
#define RPW    4            // rows per warp
#define NVAL   80           // value slots: 12 s + 66 pairs + sentinel + pad

// pair id, lexicographic i<j
constexpr int pid(int i, int j) { return i * (2 * NF - i - 1) / 2 + (j - i - 1); }

// ---------------------------------------------------------------------------
// Combo table: two 16-bit BYTE offsets into the transposed value array
// val[NVAL][4] (16 bytes per slot). combo p = val[a][r] * val[b][r].
// Slots: 0..11 = s_i, 12..77 = pairwise products, 78 = 1.0 sentinel.
// ---------------------------------------------------------------------------
struct CTbl { uint32_t v[NCOMB]; };
struct PTbl { uint32_t v[NPAIR]; };

constexpr CTbl make_ctbl() {
    CTbl t{};
    int p = 0;
    for (int i = 0; i < NF; ++i)                    // size 2: P2 * 1
        for (int j = i + 1; j < NF; ++j)
            t.v[p++] = (uint32_t)((12 + pid(i, j)) * 16)
                     | ((uint32_t)(78 * 16) << 16);
    for (int i = 0; i < NF; ++i)                    // size 3: P2(i,j) * s_k
        for (int j = i + 1; j < NF; ++j)
            for (int k = j + 1; k < NF; ++k)
                t.v[p++] = (uint32_t)((12 + pid(i, j)) * 16)
                         | ((uint32_t)(k * 16) << 16);
    for (int i = 0; i < NF; ++i)                    // size 4: P2(i,j) * P2(k,l)
        for (int j = i + 1; j < NF; ++j)
            for (int k = j + 1; k < NF; ++k)
                for (int l = k + 1; l < NF; ++l)
                    t.v[p++] = (uint32_t)((12 + pid(i, j)) * 16)
                             | ((uint32_t)((12 + pid(k, l)) * 16) << 16);
    return t;
}
constexpr PTbl make_ptbl() {
    PTbl t{};
    int p = 0;
    for (int i = 0; i < NF; ++i)
        for (int j = i + 1; j < NF; ++j)
            t.v[p++] = (uint32_t)i | ((uint32_t)j << 8);
    return t;
}

__device__ const CTbl d_ct = make_ctbl();
__device__ const PTbl d_pt = make_ptbl();

__device__ __forceinline__ float ss(float q, float inv) {
    return 1.0f - __powf(q, inv);
}

// ---------------------------------------------------------------------------
// Warp owns 4 rows; val transposed so one LDS.128 fetches an operand for all
// 4 rows. __launch_bounds__(256, 8) caps regs at 32 -> 8 blocks/SM -> the
// whole 1024-block grid is a SINGLE fully-resident wave (1184 slots).
// ---------------------------------------------------------------------------
__global__ __launch_bounds__(256, 8)
void schweizer_kernel(const float* __restrict__ x,
                      const float* __restrict__ lam_p,
                      float* __restrict__ out)
{
    __shared__ __align__(16) float val[WPB][NVAL][RPW];

    const int lane = threadIdx.x & 31;
    const int wrp  = threadIdx.x >> 5;
    const int r0   = (blockIdx.x * WPB + wrp) * RPW;

    const float lam = __ldg(lam_p);
    const float inv = 1.0f / lam;

    float (*v)[RPW] = val[wrp];

    // ---- prologue: s_i for 4 rows + passthrough columns -------------------
    #pragma unroll
    for (int e = lane; e < RPW * NF; e += 32) {          // 48 coalesced loads
        const float xv = x[(size_t)r0 * NF + e];
        const int f = e % NF, r = e / NF;
        v[f][r] = 1.0f - __powf(1.0f - xv, lam);
        out[(size_t)(r0 + r) * NCOLS + f] = xv;
    }
    if (lane < RPW) v[78][lane] = 1.0f;                  // sentinel
    __syncwarp();

    // ---- 66 pairwise products (vectorized over 4 rows) ---------------------
    #pragma unroll
    for (int p = lane; p < NPAIR; p += 32) {
        const uint32_t w = d_pt.v[p];
        const float4 a = *(const float4*)v[w & 0xFFu];
        const float4 b = *(const float4*)v[w >> 8];
        float4 r4;
        r4.x = a.x * b.x;  r4.y = a.y * b.y;
        r4.z = a.z * b.z;  r4.w = a.w * b.w;
        *(float4*)v[12 + p] = r4;
    }
    __syncwarp();

    // ---- main sweep: 24 full 32-column groups + 13-column tail -------------
    const char* vb = (const char*)v;
    float* __restrict__ o0 = out + (size_t)r0 * NCOLS + NF;
    float* __restrict__ o1 = o0 + NCOLS;
    float* __restrict__ o2 = o1 + NCOLS;
    float* __restrict__ o3 = o2 + NCOLS;

    #pragma unroll 6
    for (int k = 0; k < 24; ++k) {
        const int c = k * 32 + lane;
        const uint32_t w = d_ct.v[c];
        const float4 a = *(const float4*)(vb + (w & 0xFFFFu));
        const float4 b = *(const float4*)(vb + (w >> 16));
        o0[c] = ss(fmaf(-a.x, b.x, 1.0f), inv);
        o1[c] = ss(fmaf(-a.y, b.y, 1.0f), inv);
        o2[c] = ss(fmaf(-a.z, b.z, 1.0f), inv);
        o3[c] = ss(fmaf(-a.w, b.w, 1.0f), inv);
    }
    if (lane < NCOMB - 768) {                            // cols 768..780
        const int c = 768 + lane;
        const uint32_t w = d_ct.v[c];
        const float4 a = *(const float4*)(vb + (w & 0xFFFFu));
        const float4 b = *(const float4*)(vb + (w >> 16));
        o0[c] = ss(fmaf(-a.x, b.x, 1.0f), inv);
        o1[c] = ss(fmaf(-a.y, b.y, 1.0f), inv);
        o2[c] = ss(fmaf(-a.z, b.z, 1.0f), inv);
        o3[c] = ss(fmaf(-a.w, b.w, 1.0f), inv);
    }
}

extern "C" void kernel_launch(void* const* d_in, const int* in_sizes, int n_in,
                              void* d_out, int out_size)
{
    const float* x   = (const float*)d_in[0];
    const float* lam = (const float*)d_in[1];
    float*       out = (float*)d_out;

    schweizer_kernel<<<NROWS / (WPB * RPW), 256>>>(x, lam, out);
}

// round 7
// speedup vs baseline: 1.0254x; 1.0254x over previous
#include <cuda_runtime.h>
#include <cstdint>

#define NF     12
#define NPAIR  66
#define NCOMB  781
#define NCOLS  793
#define NROWS  32768
#define WPB    4            // warps per block
#define RPW    8            // rows per warp
#define NVAL   80           // slots: 12 s + 66 pairs + sentinel + pad

// pair id, lexicographic i<j
constexpr int pid(int i, int j) { return i * (2 * NF - i - 1) / 2 + (j - i - 1); }

// ---------------------------------------------------------------------------
// Combo table: two 16-bit BYTE offsets into the transposed value array
// val[NVAL][8] (32 bytes per slot). combo p = val[a][r] * val[b][r].
// Slots: 0..11 = s_i, 12..77 = pairwise products, 78 = 1.0 sentinel.
// ---------------------------------------------------------------------------
struct CTbl { uint32_t v[NCOMB]; };
struct PTbl { uint32_t v[NPAIR]; };

constexpr CTbl make_ctbl() {
    CTbl t{};
    int p = 0;
    for (int i = 0; i < NF; ++i)                    // size 2: P2 * 1
        for (int j = i + 1; j < NF; ++j)
            t.v[p++] = (uint32_t)((12 + pid(i, j)) * 32)
                     | ((uint32_t)(78 * 32) << 16);
    for (int i = 0; i < NF; ++i)                    // size 3: P2(i,j) * s_k
        for (int j = i + 1; j < NF; ++j)
            for (int k = j + 1; k < NF; ++k)
                t.v[p++] = (uint32_t)((12 + pid(i, j)) * 32)
                         | ((uint32_t)(k * 32) << 16);
    for (int i = 0; i < NF; ++i)                    // size 4: P2(i,j) * P2(k,l)
        for (int j = i + 1; j < NF; ++j)
            for (int k = j + 1; k < NF; ++k)
                for (int l = k + 1; l < NF; ++l)
                    t.v[p++] = (uint32_t)((12 + pid(i, j)) * 32)
                             | ((uint32_t)((12 + pid(k, l)) * 32) << 16);
    return t;
}
constexpr PTbl make_ptbl() {
    PTbl t{};
    int p = 0;
    for (int i = 0; i < NF; ++i)
        for (int j = i + 1; j < NF; ++j)
            t.v[p++] = (uint32_t)i | ((uint32_t)j << 8);
    return t;
}

__device__ const CTbl d_ct = make_ctbl();
__device__ const PTbl d_pt = make_ptbl();

__device__ __forceinline__ float ss(float a, float b, float inv) {
    return 1.0f - __powf(fmaf(-a, b, 1.0f), inv);
}

// ---------------------------------------------------------------------------
// Warp owns 8 rows. val[slot] is 32 B -> operand fetch = 2x LDS.128 for all
// 8 rows. 8 independent pow chains per column-group hide the LDS+MUFU
// latency chain. 128-thread blocks, 8 blocks/SM -> grid 1024 = single wave.
// ---------------------------------------------------------------------------
__global__ __launch_bounds__(128, 8)
void schweizer_kernel(const float* __restrict__ x,
                      const float* __restrict__ lam_p,
                      float* __restrict__ out)
{
    __shared__ __align__(16) float val[WPB][NVAL][RPW];

    const int lane = threadIdx.x & 31;
    const int wrp  = threadIdx.x >> 5;
    const int r0   = (blockIdx.x * WPB + wrp) * RPW;

    const float lam = __ldg(lam_p);
    const float inv = 1.0f / lam;

    float (*v)[RPW] = val[wrp];

    // ---- prologue: s_i for 8 rows + passthrough columns --------------------
    #pragma unroll
    for (int e = lane; e < RPW * NF; e += 32) {          // 96 coalesced loads
        const float xv = x[(size_t)r0 * NF + e];
        const int f = e % NF, r = e / NF;
        v[f][r] = 1.0f - __powf(1.0f - xv, lam);
        out[(size_t)(r0 + r) * NCOLS + f] = xv;
    }
    if (lane < RPW) v[78][lane] = 1.0f;                  // sentinel
    __syncwarp();

    // ---- 66 pairwise products (vectorized over 8 rows) ---------------------
    #pragma unroll
    for (int p = lane; p < NPAIR; p += 32) {
        const uint32_t w = d_pt.v[p];
        const float* ai = v[w & 0xFFu];
        const float* bi = v[w >> 8];
        const float4 a0 = *(const float4*)ai;
        const float4 a1 = *(const float4*)(ai + 4);
        const float4 b0 = *(const float4*)bi;
        const float4 b1 = *(const float4*)(bi + 4);
        float4 r4;
        r4.x = a0.x * b0.x;  r4.y = a0.y * b0.y;
        r4.z = a0.z * b0.z;  r4.w = a0.w * b0.w;
        *(float4*)v[12 + p] = r4;
        r4.x = a1.x * b1.x;  r4.y = a1.y * b1.y;
        r4.z = a1.z * b1.z;  r4.w = a1.w * b1.w;
        *(float4*)(v[12 + p] + 4) = r4;
    }
    __syncwarp();

    // ---- main sweep: 24 full 32-column groups + 13-column tail -------------
    const char* vb = (const char*)v;
    float* __restrict__ o = out + (size_t)r0 * NCOLS + NF;

    #pragma unroll 3
    for (int k = 0; k < 24; ++k) {
        const int c = k * 32 + lane;
        const uint32_t w = d_ct.v[c];
        const char* pa = vb + (w & 0xFFFFu);
        const char* pb = vb + (w >> 16);
        const float4 a0 = *(const float4*)pa;
        const float4 a1 = *(const float4*)(pa + 16);
        const float4 b0 = *(const float4*)pb;
        const float4 b1 = *(const float4*)(pb + 16);
        o[c]             = ss(a0.x, b0.x, inv);
        o[c + 1 * NCOLS] = ss(a0.y, b0.y, inv);
        o[c + 2 * NCOLS] = ss(a0.z, b0.z, inv);
        o[c + 3 * NCOLS] = ss(a0.w, b0.w, inv);
        o[c + 4 * NCOLS] = ss(a1.x, b1.x, inv);
        o[c + 5 * NCOLS] = ss(a1.y, b1.y, inv);
        o[c + 6 * NCOLS] = ss(a1.z, b1.z, inv);
        o[c + 7 * NCOLS] = ss(a1.w, b1.w, inv);
    }
    if (lane < NCOMB - 768) {                            // cols 768..780
        const int c = 768 + lane;
        const uint32_t w = d_ct.v[c];
        const char* pa = vb + (w & 0xFFFFu);
        const char* pb = vb + (w >> 16);
        const float4 a0 = *(const float4*)pa;
        const float4 a1 = *(const float4*)(pa + 16);
        const float4 b0 = *(const float4*)pb;
        const float4 b1 = *(const float4*)(pb + 16);
        o[c]             = ss(a0.x, b0.x, inv);
        o[c + 1 * NCOLS] = ss(a0.y, b0.y, inv);
        o[c + 2 * NCOLS] = ss(a0.z, b0.z, inv);
        o[c + 3 * NCOLS] = ss(a0.w, b0.w, inv);
        o[c + 4 * NCOLS] = ss(a1.x, b1.x, inv);
        o[c + 5 * NCOLS] = ss(a1.y, b1.y, inv);
        o[c + 6 * NCOLS] = ss(a1.z, b1.z, inv);
        o[c + 7 * NCOLS] = ss(a1.w, b1.w, inv);
    }
}

extern "C" void kernel_launch(void* const* d_in, const int* in_sizes, int n_in,
                              void* d_out, int out_size)
{
    const float* x   = (const float*)d_in[0];
    const float* lam = (const float*)d_in[1];
    float*       out = (float*)d_out;

    schweizer_kernel<<<NROWS / (WPB * RPW), WPB * 32>>>(x, lam, out);
}

// round 8
// speedup vs baseline: 1.1651x; 1.1362x over previous
#include <cuda_runtime.h>
#include <cstdint>

#define NF     12
#define NPAIR  66
#define NCOMB  781
#define NCOLS  793
#define NROWS  32768
#define WPB    8            // warps per block
#define RPW    2            // rows per warp
#define NVAL   80           // slots: 12 s + 66 pairs + sentinel + pad

// pair id, lexicographic i<j
constexpr int pid(int i, int j) { return i * (2 * NF - i - 1) / 2 + (j - i - 1); }

// ---------------------------------------------------------------------------
// Combo table: two 16-bit BYTE offsets into the transposed value array
// val[NVAL][2] (8 bytes per slot). combo p = val[a][r] * val[b][r].
// Slots: 0..11 = s_i, 12..77 = pairwise products, 78 = 1.0 sentinel.
// ---------------------------------------------------------------------------
struct CTbl { uint32_t v[NCOMB]; };
struct PTbl { uint32_t v[NPAIR]; };

constexpr CTbl make_ctbl() {
    CTbl t{};
    int p = 0;
    for (int i = 0; i < NF; ++i)                    // size 2: P2 * 1
        for (int j = i + 1; j < NF; ++j)
            t.v[p++] = (uint32_t)((12 + pid(i, j)) * 8)
                     | ((uint32_t)(78 * 8) << 16);
    for (int i = 0; i < NF; ++i)                    // size 3: P2(i,j) * s_k
        for (int j = i + 1; j < NF; ++j)
            for (int k = j + 1; k < NF; ++k)
                t.v[p++] = (uint32_t)((12 + pid(i, j)) * 8)
                         | ((uint32_t)(k * 8) << 16);
    for (int i = 0; i < NF; ++i)                    // size 4: P2(i,j) * P2(k,l)
        for (int j = i + 1; j < NF; ++j)
            for (int k = j + 1; k < NF; ++k)
                for (int l = k + 1; l < NF; ++l)
                    t.v[p++] = (uint32_t)((12 + pid(i, j)) * 8)
                             | ((uint32_t)((12 + pid(k, l)) * 8) << 16);
    return t;
}
constexpr PTbl make_ptbl() {
    PTbl t{};
    int p = 0;
    for (int i = 0; i < NF; ++i)
        for (int j = i + 1; j < NF; ++j)
            t.v[p++] = (uint32_t)i | ((uint32_t)j << 8);
    return t;
}

__device__ const CTbl d_ct = make_ctbl();
__device__ const PTbl d_pt = make_ptbl();

__device__ __forceinline__ float ss(float a, float b, float inv) {
    return 1.0f - __powf(fmaf(-a, b, 1.0f), inv);
}

// ---------------------------------------------------------------------------
// Warp owns 2 rows; val[slot] is 8 B -> one LDS.64 per operand covers both
// rows. Decode amortized 2x, regs stay ~28 -> natural 8 blocks/SM residency.
// Grid = 2048 blocks of 256 -> ~14 blocks/SM demand, high occupancy.
// ---------------------------------------------------------------------------
__global__ __launch_bounds__(256)
void schweizer_kernel(const float* __restrict__ x,
                      const float* __restrict__ lam_p,
                      float* __restrict__ out)
{
    __shared__ __align__(8) float val[WPB][NVAL][RPW];

    const int lane = threadIdx.x & 31;
    const int wrp  = threadIdx.x >> 5;
    const int r0   = (blockIdx.x * WPB + wrp) * RPW;

    const float lam = __ldg(lam_p);
    const float inv = 1.0f / lam;

    float (*v)[RPW] = val[wrp];

    // ---- prologue: s_i for 2 rows + passthrough columns --------------------
    if (lane < RPW * NF) {                               // 24 coalesced loads
        const float xv = x[(size_t)r0 * NF + lane];
        const int f = lane % NF, r = lane / NF;
        v[f][r] = 1.0f - __powf(1.0f - xv, lam);
        out[(size_t)(r0 + r) * NCOLS + f] = xv;
    } else if (lane < RPW * NF + RPW) {
        v[78][lane - RPW * NF] = 1.0f;                   // sentinel
    }
    __syncwarp();

    // ---- 66 pairwise products (vectorized over 2 rows) ---------------------
    #pragma unroll
    for (int p = lane; p < NPAIR; p += 32) {
        const uint32_t w = d_pt.v[p];
        const float2 a = *(const float2*)v[w & 0xFFu];
        const float2 b = *(const float2*)v[w >> 8];
        float2 r2;
        r2.x = a.x * b.x;
        r2.y = a.y * b.y;
        *(float2*)v[12 + p] = r2;
    }
    __syncwarp();

    // ---- main sweep: 24 full 32-column groups + 13-column tail -------------
    const char* vb = (const char*)v;
    float* __restrict__ o0 = out + (size_t)r0 * NCOLS + NF;
    float* __restrict__ o1 = o0 + NCOLS;

    #pragma unroll 4
    for (int k = 0; k < 24; ++k) {
        const int c = k * 32 + lane;
        const uint32_t w = d_ct.v[c];
        const float2 a = *(const float2*)(vb + (w & 0xFFFFu));
        const float2 b = *(const float2*)(vb + (w >> 16));
        o0[c] = ss(a.x, b.x, inv);
        o1[c] = ss(a.y, b.y, inv);
    }
    if (lane < NCOMB - 768) {                            // cols 768..780
        const int c = 768 + lane;
        const uint32_t w = d_ct.v[c];
        const float2 a = *(const float2*)(vb + (w & 0xFFFFu));
        const float2 b = *(const float2*)(vb + (w >> 16));
        o0[c] = ss(a.x, b.x, inv);
        o1[c] = ss(a.y, b.y, inv);
    }
}

extern "C" void kernel_launch(void* const* d_in, const int* in_sizes, int n_in,
                              void* d_out, int out_size)
{
    const float* x   = (const float*)d_in[0];
    const float* lam = (const float*)d_in[1];
    float*       out = (float*)d_out;

    schweizer_kernel<<<NROWS / (WPB * RPW), 256>>>(x, lam, out);
}

// round 9
// speedup vs baseline: 1.1764x; 1.0097x over previous
#include <cuda_runtime.h>
#include <cstdint>

#define NF     12
#define NPAIR  66
#define NCOMB  781
#define NCOLS  793
#define NROWS  32768
#define WPB    8            // warps per block
#define RPW    2            // rows per warp
#define NVAL   148          // slots: 0..11 s, 12..77 pairs, 78 one, 80..145 -pairs

typedef unsigned long long ull;

// pair id, lexicographic i<j
constexpr int pid(int i, int j) { return i * (2 * NF - i - 1) / 2 + (j - i - 1); }

// ---------------------------------------------------------------------------
// Combo table: two 16-bit BYTE offsets into val[NVAL][2] (8 B per slot).
// a-offset points into the NEGATED pair region (or handled so that
// q = fma(a, b, 1) = 1 - |a|*b). b-offset into the positive region.
// ---------------------------------------------------------------------------
struct CTbl { uint32_t v[NCOMB]; };
struct PTbl { uint32_t v[NPAIR]; };

constexpr CTbl make_ctbl() {
    CTbl t{};
    int p = 0;
    for (int i = 0; i < NF; ++i)                    // size 2: (-P2) * 1
        for (int j = i + 1; j < NF; ++j)
            t.v[p++] = (uint32_t)((80 + pid(i, j)) * 8)
                     | ((uint32_t)(78 * 8) << 16);
    for (int i = 0; i < NF; ++i)                    // size 3: (-P2(i,j)) * s_k
        for (int j = i + 1; j < NF; ++j)
            for (int k = j + 1; k < NF; ++k)
                t.v[p++] = (uint32_t)((80 + pid(i, j)) * 8)
                         | ((uint32_t)(k * 8) << 16);
    for (int i = 0; i < NF; ++i)                    // size 4: (-P2(i,j))*P2(k,l)
        for (int j = i + 1; j < NF; ++j)
            for (int k = j + 1; k < NF; ++k)
                for (int l = k + 1; l < NF; ++l)
                    t.v[p++] = (uint32_t)((80 + pid(i, j)) * 8)
                             | ((uint32_t)((12 + pid(k, l)) * 8) << 16);
    return t;
}
constexpr PTbl make_ptbl() {
    PTbl t{};
    int p = 0;
    for (int i = 0; i < NF; ++i)
        for (int j = i + 1; j < NF; ++j)
            t.v[p++] = (uint32_t)i | ((uint32_t)j << 8);
    return t;
}

__device__ const CTbl d_ct = make_ctbl();
__device__ const PTbl d_pt = make_ptbl();

// ---- packed f32x2 helpers (Blackwell; ptxas emits FFMA2/FMUL2 only via PTX) --
__device__ __forceinline__ ull fma2(ull a, ull b, ull c) {
    ull d; asm("fma.rn.f32x2 %0,%1,%2,%3;" : "=l"(d) : "l"(a), "l"(b), "l"(c));
    return d;
}
__device__ __forceinline__ ull mul2(ull a, ull b) {
    ull d; asm("mul.rn.f32x2 %0,%1,%2;" : "=l"(d) : "l"(a), "l"(b));
    return d;
}
__device__ __forceinline__ ull pack2(float x, float y) {
    ull r;
    asm("mov.b64 %0,{%1,%2};" : "=l"(r)
        : "r"(__float_as_uint(x)), "r"(__float_as_uint(y)));
    return r;
}
__device__ __forceinline__ void unpack2(ull v, float& x, float& y) {
    uint32_t a, b;
    asm("mov.b64 {%0,%1},%2;" : "=r"(a), "=r"(b) : "l"(v));
    x = __uint_as_float(a); y = __uint_as_float(b);
}
__device__ __forceinline__ float lg2a(float x) {
    float r; asm("lg2.approx.f32 %0,%1;" : "=f"(r) : "f"(x)); return r;
}
__device__ __forceinline__ float ex2a(float x) {
    float r; asm("ex2.approx.f32 %0,%1;" : "=f"(r) : "f"(x)); return r;
}

// ---------------------------------------------------------------------------
__global__ __launch_bounds__(256)
void schweizer_kernel(const float* __restrict__ x,
                      const float* __restrict__ lam_p,
                      float* __restrict__ out)
{
    __shared__ __align__(8) float val[WPB][NVAL][RPW];

    const int lane = threadIdx.x & 31;
    const int wrp  = threadIdx.x >> 5;
    const int r0   = (blockIdx.x * WPB + wrp) * RPW;

    const float lam = __ldg(lam_p);
    const float inv = 1.0f / lam;

    const ull ONES = pack2(1.0f, 1.0f);
    const ull MN1  = pack2(-1.0f, -1.0f);
    const ull INV2 = pack2(inv, inv);

    float (*v)[RPW] = val[wrp];

    // ---- prologue: s_i for 2 rows + passthrough --------------------------
    if (lane < RPW * NF) {
        const float xv = x[(size_t)r0 * NF + lane];
        const int f = lane % NF, r = lane / NF;
        v[f][r] = 1.0f - __powf(1.0f - xv, lam);
        out[(size_t)(r0 + r) * NCOLS + f] = xv;
    } else if (lane < RPW * NF + RPW) {
        v[78][lane - RPW * NF] = 1.0f;                   // sentinel
    }
    __syncwarp();

    // ---- 66 pairwise products + negated copies ----------------------------
    #pragma unroll
    for (int p = lane; p < NPAIR; p += 32) {
        const uint32_t w = d_pt.v[p];
        const float2 a = *(const float2*)v[w & 0xFFu];
        const float2 b = *(const float2*)v[w >> 8];
        float2 r2, n2;
        r2.x = a.x * b.x;  r2.y = a.y * b.y;
        n2.x = -r2.x;      n2.y = -r2.y;
        *(float2*)v[12 + p] = r2;
        *(float2*)v[80 + p] = n2;
    }
    __syncwarp();

    // ---- main sweep: 24 full 32-column groups + 13-column tail ------------
    const char* vb = (const char*)v;
    float* __restrict__ o0 = out + (size_t)r0 * NCOLS + NF;
    float* __restrict__ o1 = o0 + NCOLS;

    #pragma unroll 4
    for (int k = 0; k < 24; ++k) {
        const int c = k * 32 + lane;
        const uint32_t w = d_ct.v[c];
        const ull A = *(const ull*)(vb + (w & 0xFFFFu));  // (-a0, -a1)
        const ull B = *(const ull*)(vb + (w >> 16));      // ( b0,  b1)
        const ull Q = fma2(A, B, ONES);                   // 1 - a*b (both rows)
        float q0, q1; unpack2(Q, q0, q1);
        const ull M = mul2(pack2(lg2a(q0), lg2a(q1)), INV2);
        float m0, m1; unpack2(M, m0, m1);
        const ull R = fma2(pack2(ex2a(m0), ex2a(m1)), MN1, ONES); // 1 - q^inv
        float r0v, r1v; unpack2(R, r0v, r1v);
        o0[c] = r0v;
        o1[c] = r1v;
    }
    if (lane < NCOMB - 768) {                             // cols 768..780
        const int c = 768 + lane;
        const uint32_t w = d_ct.v[c];
        const float* pa = (const float*)(vb + (w & 0xFFFFu));
        const float* pb = (const float*)(vb + (w >> 16));
        const float q0 = fmaf(pa[0], pb[0], 1.0f);
        const float q1 = fmaf(pa[1], pb[1], 1.0f);
        o0[c] = 1.0f - ex2a(lg2a(q0) * inv);
        o1[c] = 1.0f - ex2a(lg2a(q1) * inv);
    }
}

extern "C" void kernel_launch(void* const* d_in, const int* in_sizes, int n_in,
                              void* d_out, int out_size)
{
    const float* x   = (const float*)d_in[0];
    const float* lam = (const float*)d_in[1];
    float*       out = (float*)d_out;

    schweizer_kernel<<<NROWS / (WPB * RPW), 256>>>(x, lam, out);
}